// round 13
// baseline (speedup 1.0000x reference)
#include <cuda_runtime.h>

#define NB        256            // bins per batch
#define TB        1024           // bucket-table size (== BLOCK)
#define BLOCK     1024           // threads per block
#define BPB       74             // blocks per batch: 4*74=296 = 2/SM, 64 warps/SM
#define MAXB      8
#define NGAP      (NB + 1)
#define GAPSTRIDE 8              // 32B per global gap slot

// Static zero-init scratch; counters/gap slots reset in-kernel before exit.
__device__ unsigned g_gapmax [MAXB * NGAP * GAPSTRIDE];  // max of float bits (pv>0)
__device__ unsigned g_gapminN[MAXB * NGAP * GAPSTRIDE];  // max of ~bits
__device__ float    g_sorted[MAXB * NB];
__device__ float    g_psum[MAXB * BPB];
__device__ float    g_pcnt[MAXB * BPB];
__device__ unsigned g_arrive;

__device__ __forceinline__ float vldf(const float* p) { return *(const volatile float*)p; }
__device__ __forceinline__ unsigned vldu(const unsigned* p) { return *(const volatile unsigned*)p; }

// per-point hot path: 1 LDS.128 table + predicate select + 1 LDS.64 gap check.
__device__ __forceinline__ void ppoint(
    float pv, const uint4* __restrict__ tab, const float* __restrict__ sc,
    uint2* gap, float lo, float scale, float& sumA, float& cnt)
{
    int k = __float2int_rd((pv - lo) * scale);
    k = min(TB - 1, max(k, 0));
    uint4 e = tab[k];
    int g; float cl, cr;
    if (e.w >> 16) {                      // rare: >=2 bins in bucket, short narrow
        int a = (int)(e.w & 0xffffu), b2 = (int)(e.w >> 16);
        while (a < b2) { int m = (a + b2) >> 1; if (sc[m] <= pv) a = m + 1; else b2 = m; }
        g = a;
        cl = (g > 0)  ? sc[g - 1] : -3e18f;
        cr = (g < NB) ? sc[g]     :  3e18f;
    } else {
        float cm = __uint_as_float(e.y);
        bool pr = pv >= cm;               // ties: bin <= pv counts -> g+1
        cl = pr ? cm : __uint_as_float(e.x);
        cr = pr ? __uint_as_float(e.z) : cm;
        g = (int)e.w + (pr ? 1 : 0);
    }
    float dlo = pv - cl, dhi = cr - pv;
    float d = fminf(dlo * dlo, dhi * dhi);
    if (pv >= 0.001f) {                   // same mask constant as reference
        sumA += d; cnt += 1.0f;
        unsigned pb = __float_as_uint(pv);        // pv>0: uint order == float order
        uint2 cur = gap[g];
        if (pb > cur.x)  atomicMax(&gap[g].x, pb);   // monotonic -> stale-skip safe
        unsigned nb2 = ~pb;
        if (nb2 > cur.y) atomicMax(&gap[g].y, nb2);
    }
}

__global__ void __launch_bounds__(BLOCK, 2)
k_all(const float* __restrict__ bins, const float* __restrict__ pts,
      int V, int B, float* __restrict__ out)
{
    __shared__ __align__(16) union {
        uint4 tab[TB];                    // 16 KB, final
        int   hist[TB];                   // 4 KB, prep
    } u;
    __shared__ unsigned short Gt[TB + 1];
    __shared__ __align__(16) float sval[NB];
    __shared__ float          sc[NB];
    __shared__ uint2          gap[NGAP];
    __shared__ float          red[32], red2[32];
    __shared__ float          s_above[BLOCK];     // 4 groups x 256
    __shared__ float          sh_sA[MAXB], sh_n[MAXB], sh_mc2[MAXB];
    __shared__ float          sh_S1[MAXB], sh_S2[MAXB];
    __shared__ float          s_lo, s_scale;
    __shared__ int            s_fin;

    const int b = blockIdx.y, bx = blockIdx.x, t = threadIdx.x;
    const int lane = t & 31, w = t >> 5;

    // ---- prefetch this thread's points as float2 (overlaps with prep) --------
    const float* pf = pts + (size_t)b * V;
    const int V2 = V >> 1;                // 78848
    const float2* p2 = reinterpret_cast<const float2*>(pf);
    const int S = BPB * BLOCK;            // 75776
    const int i0 = bx * BLOCK + t;        // < 75776 <= V2 always
    float2 q0, q1;
    const bool v1 = i0 + S < V2;          // first 3072 threads only
    q0 = p2[i0];
    if (v1) q1 = p2[i0 + S];

    // ---- load bins, init hist + gap tallies -----------------------------------
    if (t < NB) sval[t] = bins[b * NB + t];
    u.hist[t] = 0;                        // TB == BLOCK
    if (t < NGAP) gap[t] = make_uint2(0u, 0u);
    __syncthreads();

    // ---- min/max of bins -> bucket transform ------------------------------------
    {
        float v = (t < NB) ? sval[t] : sval[0];
        float mn = v, mx = v;
#pragma unroll
        for (int o = 16; o; o >>= 1) {
            mn = fminf(mn, __shfl_down_sync(0xffffffffu, mn, o));
            mx = fmaxf(mx, __shfl_down_sync(0xffffffffu, mx, o));
        }
        if (lane == 0 && w < 8) { red[w] = mn; red2[w] = mx; }
    }
    __syncthreads();
    if (w == 0) {                         // warp 0 combines 8 partials by shuffle
        float mn = (lane < 8) ? red[lane]  :  3e18f;
        float mx = (lane < 8) ? red2[lane] : -3e18f;
#pragma unroll
        for (int o = 4; o; o >>= 1) {
            mn = fminf(mn, __shfl_down_sync(0xffffffffu, mn, o));
            mx = fmaxf(mx, __shfl_down_sync(0xffffffffu, mx, o));
        }
        if (lane == 0) {
            float d = mx - mn;
            s_lo = mn;
            s_scale = (d > 1e-30f) ? ((float)TB / d) : 0.0f;
        }
    }
    __syncthreads();
    const float lo = s_lo, scale = s_scale;

    // ---- histogram of bin buckets -------------------------------------------------
    int kbv = 0;
    if (t < NB) {
        kbv = __float2int_rd((sval[t] - lo) * scale);
        kbv = min(TB - 1, max(kbv, 0));
        atomicAdd(&u.hist[kbv], 1);
    }
    __syncthreads();

    // ---- exclusive scan hist -> Gt (two-level shuffle scan) -------------------------
    {
        int h = u.hist[t];
        u.hist[t] = 0;                    // reuse as slot counters
        int incl = h;
#pragma unroll
        for (int o = 1; o < 32; o <<= 1) {
            int uu = __shfl_up_sync(0xffffffffu, incl, o);
            if (lane >= o) incl += uu;
        }
        if (lane == 31) red[w] = __int_as_float(incl);
        __syncthreads();
        if (w == 0) {                     // warp 0: exclusive scan of 32 partials
            int v = __float_as_int(red[lane]);
            int si = v;
#pragma unroll
            for (int o = 1; o < 32; o <<= 1) {
                int uu = __shfl_up_sync(0xffffffffu, si, o);
                if (lane >= o) si += uu;
            }
            red[lane] = __int_as_float(si - v);
        }
        __syncthreads();
        int base = __float_as_int(red[w]) + incl - h;
        Gt[t] = (unsigned short)base;
        if (t == BLOCK - 1) Gt[TB] = (unsigned short)(base + h);
    }
    __syncthreads();

    // ---- placement: atomic slot within bucket; O(m) re-rank for collisions ---------
    float myv = 0.0f; int aslot = 0, abase = 0, mcount = 0;
    if (t < NB) {
        myv = sval[t];
        abase = Gt[kbv];
        mcount = Gt[kbv + 1] - abase;
        int off = (mcount == 1) ? 0 : atomicAdd(&u.hist[kbv], 1);
        aslot = abase + off;
        sc[aslot] = myv;
    }
    __syncthreads();
    int rrank = 0;
    if (t < NB && mcount > 1) {
        for (int j = abase; j < abase + mcount; j++) {
            float vj = sc[j];
            rrank += (vj < myv) || (vj == myv && j < aslot);
        }
    }
    __syncthreads();
    if (t < NB && mcount > 1) sc[abase + rrank] = myv;
    __syncthreads();

    // ---- three-candidate direct-answer table (one entry/thread) ---------------------
    {
        int k = t;
        int a = Gt[k], b2 = Gt[k + 1], m = b2 - a;
        uint4 e;
        if (m <= 1) {
            float prev = (a > 0) ? sc[a - 1] : -3e18f;
            if (m == 0) {
                float cr = (a < NB) ? sc[a] : 3e18f;
                e.x = __float_as_uint(prev); e.y = __float_as_uint(cr);
                e.z = __float_as_uint(cr);   e.w = (unsigned)a;
            } else {
                float cm  = sc[a];
                float nxt = (a + 1 < NB) ? sc[a + 1] : 3e18f;
                e.x = __float_as_uint(prev); e.y = __float_as_uint(cm);
                e.z = __float_as_uint(nxt);  e.w = (unsigned)a;
            }
        } else {
            e.x = 0u; e.y = 0u; e.z = 0u;
            e.w = (unsigned)a | ((unsigned)b2 << 16);
        }
        u.tab[k] = e;
    }
    __syncthreads();

    // ================= MAIN PASS ======================================================
    float sumA = 0.0f, cnt = 0.0f;
    ppoint(q0.x, u.tab, sc, gap, lo, scale, sumA, cnt);
    ppoint(q0.y, u.tab, sc, gap, lo, scale, sumA, cnt);
    if (v1) {
        ppoint(q1.x, u.tab, sc, gap, lo, scale, sumA, cnt);
        ppoint(q1.y, u.tab, sc, gap, lo, scale, sumA, cnt);
    }
    for (int i = i0 + 2 * S; i < V2; i += S) {   // generic remainder (unused here)
        float2 q = p2[i];
        ppoint(q.x, u.tab, sc, gap, lo, scale, sumA, cnt);
        ppoint(q.y, u.tab, sc, gap, lo, scale, sumA, cnt);
    }
    if (bx == 0 && t == 0 && (V & 1))
        ppoint(pf[V - 1], u.tab, sc, gap, lo, scale, sumA, cnt);

    // ---- block reduction of sumA / cnt (two-level shuffle) ---------------------------
#pragma unroll
    for (int o = 16; o; o >>= 1) {
        sumA += __shfl_down_sync(0xffffffffu, sumA, o);
        cnt  += __shfl_down_sync(0xffffffffu, cnt,  o);
    }
    if (lane == 0) { red[w] = sumA; red2[w] = cnt; }
    __syncthreads();
    if (w == 0) {                         // warp 0 reduces 32 partials
        float s = red[lane], c = red2[lane];
#pragma unroll
        for (int o = 16; o; o >>= 1) {
            s += __shfl_down_sync(0xffffffffu, s, o);
            c += __shfl_down_sync(0xffffffffu, c, o);
        }
        if (lane == 0) {
            g_psum[b * BPB + bx] = s;
            g_pcnt[b * BPB + bx] = c;
        }
    }

    // ---- flush shared gap tallies + publish sorted bins --------------------------------
    if (t < NGAP) {
        uint2 v = gap[t];
        if (v.x) atomicMax(&g_gapmax [(b * NGAP + t) * GAPSTRIDE], v.x);
        if (v.y) atomicMax(&g_gapminN[(b * NGAP + t) * GAPSTRIDE], v.y);
    }
    if (bx == 0 && t < NB) g_sorted[b * NB + t] = sc[t];

    // ---- single global arrival: last block of ALL does fused finalize ------------------
    __threadfence();
    __syncthreads();
    if (t == 0) {
        unsigned total = gridDim.x * gridDim.y;
        unsigned old = atomicAdd(&g_arrive, 1u);
        s_fin = (old == total - 1u) ? 1 : 0;
    }
    __syncthreads();
    if (!s_fin) return;
    __threadfence();

    // ================= FUSED FINALIZE: 4 batches in parallel warp-groups =================
    // All global inputs loaded up front (independent LDGs -> one latency), then
    // every phase is shuffle/barrier-only.
    const int wt  = t & 255;              // bin index within group
    const int wiw = (t >> 5) & 7;         // warp within group (0..7)
    const int NWP = (BPB + 31) / 32;      // warps holding psum partials
    const int bb  = t >> 8;               // batch handled by this group (B==4)
    const bool act = bb < B;
    const int gbase = (t >> 8) * 8;       // this group's warps in red[]

    // ---- bulk loads ----
    float ps = 0.0f, pc = 0.0f;
    if (act && wt < BPB) { ps = vldf(&g_psum[bb * BPB + wt]); pc = vldf(&g_pcnt[bb * BPB + wt]); }
    float c = act ? vldf(&g_sorted[bb * NB + wt]) : 3e18f;
    unsigned mb = act ? vldu(&g_gapmax [(bb * NGAP + wt) * GAPSTRIDE]) : 0u;
    unsigned na = act ? vldu(&g_gapminN[(bb * NGAP + (NB - wt)) * GAPSTRIDE]) : 0u;
    float c2 = act ? c * c : 3e18f;

    // ---- sumA_b / n_b ----
    {
        float s = ps, cc = pc;
#pragma unroll
        for (int o = 16; o; o >>= 1) {
            s  += __shfl_down_sync(0xffffffffu, s,  o);
            cc += __shfl_down_sync(0xffffffffu, cc, o);
        }
        if (lane == 0) { red[w] = s; red2[w] = cc; }
    }
    __syncthreads();
    if (act && wt == 0) {
        float ss = 0.0f, cc = 0.0f;
        for (int i = 0; i < NWP; i++) { ss += red[gbase + i]; cc += red2[gbase + i]; }
        sh_sA[bb] = ss; sh_n[bb] = cc;
    }
    __syncthreads();

    // ---- minc2 per group ----
    {
        float m = c2;
#pragma unroll
        for (int o = 16; o; o >>= 1) m = fminf(m, __shfl_down_sync(0xffffffffu, m, o));
        if (lane == 0) red[w] = m;
    }
    __syncthreads();
    if (act && wt == 0) {
        float mc = red[gbase];
        for (int i = 1; i < 8; i++) mc = fminf(mc, red[gbase + i]);
        sh_mc2[bb] = mc;
    }
    __syncthreads();

    // ---- nearest valid point BELOW bin wt: prefix-max of gap maxes 0..wt ----
    float below = (mb == 0u) ? -3e18f : __uint_as_float(mb);
#pragma unroll
    for (int o = 1; o < 32; o <<= 1) {
        float uu = __shfl_up_sync(0xffffffffu, below, o);
        if (lane >= o) below = fmaxf(below, uu);
    }
    if (lane == 31) red2[w] = below;
    __syncthreads();
    {
        float carry = -3e18f;
        for (int i = 0; i < wiw; i++) carry = fmaxf(carry, red2[gbase + i]);
        below = fmaxf(below, carry);
    }
    __syncthreads();

    // ---- nearest valid point ABOVE bin j: suffix-min of gap mins j+1..256 ----
    float above = (na == 0u) ? 3e18f : __uint_as_float(~na);
#pragma unroll
    for (int o = 1; o < 32; o <<= 1) {
        float uu = __shfl_up_sync(0xffffffffu, above, o);
        if (lane >= o) above = fminf(above, uu);
    }
    if (lane == 31) red2[w] = above;
    __syncthreads();
    {
        float carry2 = 3e18f;
        for (int i = 0; i < wiw; i++) carry2 = fminf(carry2, red2[gbase + i]);
        above = fminf(above, carry2);
    }
    s_above[t] = above;
    __syncthreads();

    // ---- per-bin minima + sums ----
    float mv1 = 0.0f, mv2 = 0.0f;
    if (act) {
        float ab = s_above[(t & ~255) + (NB - 1 - wt)];
        float d1 = c - below;          // sentinels -> ~9e36, never the min
        float d2 = ab - c;
        mv1 = fminf(d1 * d1, d2 * d2); // min over valid points
        mv2 = fminf(mv1, c2);          // incl. zero pad-point candidate
    }
#pragma unroll
    for (int o = 16; o; o >>= 1) {
        mv1 += __shfl_down_sync(0xffffffffu, mv1, o);
        mv2 += __shfl_down_sync(0xffffffffu, mv2, o);
    }
    if (lane == 0) { red[w] = mv1; red2[w] = mv2; }
    __syncthreads();
    if (act && wt == 0) {
        float S1 = 0.0f, S2 = 0.0f;
        for (int i = 0; i < 8; i++) { S1 += red[gbase + i]; S2 += red2[gbase + i]; }
        sh_S1[bb] = S1; sh_S2[bb] = S2;
    }
    __syncthreads();

    if (t == 0) {
        float Lmax = 0.0f;
        for (int bb2 = 0; bb2 < B; bb2++) Lmax = fmaxf(Lmax, sh_n[bb2]);
        float total = 0.0f;
        for (int bb2 = 0; bb2 < B; bb2++) {
            float npad = Lmax - sh_n[bb2];
            total += sh_sA[bb2] + npad * sh_mc2[bb2]
                   + ((npad > 0.0f) ? sh_S2[bb2] : sh_S1[bb2]);
        }
        out[0] = total / (float)B;
    }

    // ---- reset all scratch for next replay (all reads above complete) ------------------
    __syncthreads();
    for (int i = t; i < B * NGAP; i += BLOCK) {
        g_gapmax [i * GAPSTRIDE] = 0u;
        g_gapminN[i * GAPSTRIDE] = 0u;
    }
    if (t == 0) g_arrive = 0u;
}

// -----------------------------------------------------------------------------
extern "C" void kernel_launch(void* const* d_in, const int* in_sizes, int n_in,
                              void* d_out, int out_size)
{
    const float* bins = (const float*)d_in[0];
    const float* pts  = (const float*)d_in[1];
    int sb = in_sizes[0], sp = in_sizes[1];
    if (sb > sp) {                 // defensive: detect swapped input order
        const float* tmp = bins; bins = pts; pts = tmp;
        int ts = sb; sb = sp; sp = ts;
    }
    int B = sb / NB;               // 4
    int V = sp / B;                // 157696

    dim3 grid(BPB, B);
    k_all<<<grid, BLOCK>>>(bins, pts, V, B, (float*)d_out);
}

// round 14
// speedup vs baseline: 1.0133x; 1.0133x over previous
#include <cuda_runtime.h>

#define NB        256            // bins per batch
#define TB        512            // bucket-table size
#define BLOCK     1024           // threads per block
#define BPB       74             // blocks per batch: 4*74=296 = 2/SM, 64 warps/SM
#define MAXB      8
#define NGAP      (NB + 1)
#define GAPSTRIDE 8              // 32B per global gap slot

// Static zero-init scratch; counters/gap slots reset in-kernel before exit.
__device__ unsigned g_gapmax [MAXB * NGAP * GAPSTRIDE];  // max of float bits (pv>0)
__device__ unsigned g_gapminN[MAXB * NGAP * GAPSTRIDE];  // max of ~bits
__device__ float    g_sorted[MAXB * NB];
__device__ float    g_psum[MAXB * BPB];
__device__ float    g_pcnt[MAXB * BPB];
__device__ unsigned g_arrive;

__device__ __forceinline__ float vldf(const float* p) { return *(const volatile float*)p; }
__device__ __forceinline__ unsigned vldu(const unsigned* p) { return *(const volatile unsigned*)p; }

// per-point hot path: 1 LDS.128 table + predicate select + 1 LDS.64 gap check.
__device__ __forceinline__ void ppoint(
    float pv, const uint4* __restrict__ tab, const float* __restrict__ sc,
    uint2* gap, float lo, float scale, float& sumA, float& cnt)
{
    int k = __float2int_rd((pv - lo) * scale);
    k = min(TB - 1, max(k, 0));
    uint4 e = tab[k];
    int g; float cl, cr;
    if (e.w >> 16) {                      // boundary bucket (>=2 bins): short narrow
        int a = (int)(e.w & 0xffffu), b2 = (int)(e.w >> 16);
        while (a < b2) { int m = (a + b2) >> 1; if (sc[m] <= pv) a = m + 1; else b2 = m; }
        g = a;
        cl = (g > 0)  ? sc[g - 1] : -3e18f;
        cr = (g < NB) ? sc[g]     :  3e18f;
    } else {
        float cm = __uint_as_float(e.y);
        bool pr = pv >= cm;               // ties: bin <= pv counts -> g+1
        cl = pr ? cm : __uint_as_float(e.x);
        cr = pr ? __uint_as_float(e.z) : cm;
        g = (int)e.w + (pr ? 1 : 0);
    }
    float dlo = pv - cl, dhi = cr - pv;
    float d = fminf(dlo * dlo, dhi * dhi);
    if (pv >= 0.001f) {                   // same mask constant as reference
        sumA += d; cnt += 1.0f;
        unsigned pb = __float_as_uint(pv);        // pv>0: uint order == float order
        uint2 cur = gap[g];
        if (pb > cur.x)  atomicMax(&gap[g].x, pb);   // monotonic -> stale-skip safe
        unsigned nb2 = ~pb;
        if (nb2 > cur.y) atomicMax(&gap[g].y, nb2);
    }
}

__global__ void __launch_bounds__(BLOCK, 2)
k_all(const float* __restrict__ bins, const float* __restrict__ pts,
      int V, int B, float* __restrict__ out)
{
    __shared__ __align__(16) union {
        uint4 tab[TB];                    // 8 KB, final
        int   hist[TB];                   // 2 KB, prep
    } u;
    __shared__ unsigned short Gt[TB + 1];
    __shared__ float          sc[NB];
    __shared__ uint2          gap[NGAP];
    __shared__ float          red[32], red2[32];
    __shared__ float          s_above[BLOCK];     // 4 groups x 256
    __shared__ float          sh_sA[MAXB], sh_n[MAXB], sh_mc2[MAXB];
    __shared__ float          sh_S1[MAXB], sh_S2[MAXB];
    __shared__ float          s_lo, s_scale;
    __shared__ int            s_fin;

    const int b = blockIdx.y, bx = blockIdx.x, t = threadIdx.x;
    const int lane = t & 31, w = t >> 5;

    // ---- prefetch this thread's points as float2 (overlaps with prep) --------
    const float* pf = pts + (size_t)b * V;
    const int V2 = V >> 1;                // 78848
    const float2* p2 = reinterpret_cast<const float2*>(pf);
    const int S = BPB * BLOCK;            // 75776
    const int i0 = bx * BLOCK + t;        // < 75776 <= V2 always
    float2 q0, q1;
    const bool v1 = i0 + S < V2;          // first 3072 threads only
    q0 = p2[i0];
    if (v1) q1 = p2[i0 + S];

    // ---- bins in registers; init hist + gap tallies ----------------------------
    const bool isbin = t < NB;
    float bv = isbin ? bins[b * NB + t] : 0.0f;
    if (t < TB) u.hist[t] = 0;
    if (t < NGAP) gap[t] = make_uint2(0u, 0u);

    // ---- min/max of bins -> bucket transform ------------------------------------
    {
        float v = isbin ? bv : (isbin, bv);    // placeholder; handled below
        float mn = isbin ? bv :  3e18f;
        float mx = isbin ? bv : -3e18f;
#pragma unroll
        for (int o = 16; o; o >>= 1) {
            mn = fminf(mn, __shfl_down_sync(0xffffffffu, mn, o));
            mx = fmaxf(mx, __shfl_down_sync(0xffffffffu, mx, o));
        }
        if (lane == 0 && w < 8) { red[w] = mn; red2[w] = mx; }
        (void)v;
    }
    __syncthreads();                       // also covers hist/gap init
    if (w == 0) {                          // warp 0 combines 8 partials by shuffle
        float mn = (lane < 8) ? red[lane]  :  3e18f;
        float mx = (lane < 8) ? red2[lane] : -3e18f;
#pragma unroll
        for (int o = 4; o; o >>= 1) {
            mn = fminf(mn, __shfl_down_sync(0xffffffffu, mn, o));
            mx = fmaxf(mx, __shfl_down_sync(0xffffffffu, mx, o));
        }
        if (lane == 0) {
            float d = mx - mn;
            s_lo = mn;
            s_scale = (d > 1e-30f) ? ((float)TB / d) : 0.0f;
        }
    }
    __syncthreads();
    const float lo = s_lo, scale = s_scale;

    // ---- histogram of bin buckets -------------------------------------------------
    int kbv = 0;
    if (isbin) {
        kbv = __float2int_rd((bv - lo) * scale);
        kbv = min(TB - 1, max(kbv, 0));
        atomicAdd(&u.hist[kbv], 1);
    }
    __syncthreads();

    // ---- exclusive scan hist -> Gt (two-level shuffle scan, 16 warps) ---------------
    {
        int h = 0, incl = 0;
        if (t < TB) {
            h = u.hist[t];
            u.hist[t] = 0;                // reuse as slot counters
            incl = h;
#pragma unroll
            for (int o = 1; o < 32; o <<= 1) {
                int uu = __shfl_up_sync(0xffffffffu, incl, o);
                if (lane >= o) incl += uu;
            }
            if (lane == 31) red[w] = __int_as_float(incl);
        }
        __syncthreads();
        if (w == 0) {                     // warp 0: exclusive scan of 16 partials
            int v = (lane < TB / 32) ? __float_as_int(red[lane]) : 0;
            int si = v;
#pragma unroll
            for (int o = 1; o < 32; o <<= 1) {
                int uu = __shfl_up_sync(0xffffffffu, si, o);
                if (lane >= o) si += uu;
            }
            red[lane] = __int_as_float(si - v);
        }
        __syncthreads();
        if (t < TB) {
            int base = __float_as_int(red[w]) + incl - h;
            Gt[t] = (unsigned short)base;
            if (t == TB - 1) Gt[TB] = (unsigned short)(base + h);
        }
    }
    __syncthreads();

    // ---- placement: atomic slot within bucket; O(m) re-rank for collisions ---------
    int aslot = 0, abase = 0, mcount = 0;
    if (isbin) {
        abase = Gt[kbv];
        mcount = Gt[kbv + 1] - abase;
        int off = (mcount == 1) ? 0 : atomicAdd(&u.hist[kbv], 1);
        aslot = abase + off;
        sc[aslot] = bv;
    }
    __syncthreads();
    int rrank = 0;
    if (isbin && mcount > 1) {
        for (int j = abase; j < abase + mcount; j++) {
            float vj = sc[j];
            rrank += (vj < bv) || (vj == bv && j < aslot);
        }
    }
    __syncthreads();
    if (isbin && mcount > 1) sc[abase + rrank] = bv;
    __syncthreads();

    // ---- three-candidate direct-answer table (threads < TB) --------------------------
    if (t < TB) {
        int k = t;
        int a = Gt[k], b2 = Gt[k + 1], m = b2 - a;
        uint4 e;
        if (m <= 1) {
            float prev = (a > 0) ? sc[a - 1] : -3e18f;
            if (m == 0) {
                float cr = (a < NB) ? sc[a] : 3e18f;
                e.x = __float_as_uint(prev); e.y = __float_as_uint(cr);
                e.z = __float_as_uint(cr);   e.w = (unsigned)a;
            } else {
                float cm  = sc[a];
                float nxt = (a + 1 < NB) ? sc[a + 1] : 3e18f;
                e.x = __float_as_uint(prev); e.y = __float_as_uint(cm);
                e.z = __float_as_uint(nxt);  e.w = (unsigned)a;
            }
        } else {
            e.x = 0u; e.y = 0u; e.z = 0u;
            e.w = (unsigned)a | ((unsigned)b2 << 16);
        }
        u.tab[k] = e;
    }
    __syncthreads();

    // ================= MAIN PASS ======================================================
    float sumA = 0.0f, cnt = 0.0f;
    ppoint(q0.x, u.tab, sc, gap, lo, scale, sumA, cnt);
    ppoint(q0.y, u.tab, sc, gap, lo, scale, sumA, cnt);
    if (v1) {
        ppoint(q1.x, u.tab, sc, gap, lo, scale, sumA, cnt);
        ppoint(q1.y, u.tab, sc, gap, lo, scale, sumA, cnt);
    }
    for (int i = i0 + 2 * S; i < V2; i += S) {   // generic remainder (unused here)
        float2 q = p2[i];
        ppoint(q.x, u.tab, sc, gap, lo, scale, sumA, cnt);
        ppoint(q.y, u.tab, sc, gap, lo, scale, sumA, cnt);
    }
    if (bx == 0 && t == 0 && (V & 1))
        ppoint(pf[V - 1], u.tab, sc, gap, lo, scale, sumA, cnt);

    // ---- block reduction of sumA / cnt (two-level shuffle) ---------------------------
#pragma unroll
    for (int o = 16; o; o >>= 1) {
        sumA += __shfl_down_sync(0xffffffffu, sumA, o);
        cnt  += __shfl_down_sync(0xffffffffu, cnt,  o);
    }
    if (lane == 0) { red[w] = sumA; red2[w] = cnt; }
    __syncthreads();
    if (w == 0) {                         // warp 0 reduces 32 partials
        float s = red[lane], c = red2[lane];
#pragma unroll
        for (int o = 16; o; o >>= 1) {
            s += __shfl_down_sync(0xffffffffu, s, o);
            c += __shfl_down_sync(0xffffffffu, c, o);
        }
        if (lane == 0) {
            g_psum[b * BPB + bx] = s;
            g_pcnt[b * BPB + bx] = c;
        }
    }

    // ---- flush shared gap tallies + publish sorted bins --------------------------------
    if (t < NGAP) {
        uint2 v = gap[t];
        if (v.x) atomicMax(&g_gapmax [(b * NGAP + t) * GAPSTRIDE], v.x);
        if (v.y) atomicMax(&g_gapminN[(b * NGAP + t) * GAPSTRIDE], v.y);
    }
    if (bx == 0 && t < NB) g_sorted[b * NB + t] = sc[t];

    // ---- single global arrival: last block of ALL does fused finalize ------------------
    __threadfence();
    __syncthreads();
    if (t == 0) {
        unsigned total = gridDim.x * gridDim.y;
        unsigned old = atomicAdd(&g_arrive, 1u);
        s_fin = (old == total - 1u) ? 1 : 0;
    }
    __syncthreads();
    if (!s_fin) return;
    __threadfence();

    // ================= FUSED FINALIZE: 4 batches in parallel warp-groups =================
    // All global inputs loaded up front (independent LDGs -> one latency).
    const int wt  = t & 255;              // bin index within group
    const int wiw = (t >> 5) & 7;         // warp within group (0..7)
    const int NWP = (BPB + 31) / 32;      // warps holding psum partials
    const int bb  = t >> 8;               // batch handled by this group (B==4)
    const bool act = bb < B;
    const int gbase = (t >> 8) * 8;       // this group's warps in red[]

    // ---- bulk loads ----
    float ps = 0.0f, pc = 0.0f;
    if (act && wt < BPB) { ps = vldf(&g_psum[bb * BPB + wt]); pc = vldf(&g_pcnt[bb * BPB + wt]); }
    float c = act ? vldf(&g_sorted[bb * NB + wt]) : 3e18f;
    unsigned mb = act ? vldu(&g_gapmax [(bb * NGAP + wt) * GAPSTRIDE]) : 0u;
    unsigned na = act ? vldu(&g_gapminN[(bb * NGAP + (NB - wt)) * GAPSTRIDE]) : 0u;
    float c2 = act ? c * c : 3e18f;

    // ---- sumA_b / n_b ----
    {
        float s = ps, cc = pc;
#pragma unroll
        for (int o = 16; o; o >>= 1) {
            s  += __shfl_down_sync(0xffffffffu, s,  o);
            cc += __shfl_down_sync(0xffffffffu, cc, o);
        }
        if (lane == 0) { red[w] = s; red2[w] = cc; }
    }
    __syncthreads();
    if (act && wt == 0) {
        float ss = 0.0f, cc = 0.0f;
        for (int i = 0; i < NWP; i++) { ss += red[gbase + i]; cc += red2[gbase + i]; }
        sh_sA[bb] = ss; sh_n[bb] = cc;
    }
    __syncthreads();

    // ---- minc2 per group ----
    {
        float m = c2;
#pragma unroll
        for (int o = 16; o; o >>= 1) m = fminf(m, __shfl_down_sync(0xffffffffu, m, o));
        if (lane == 0) red[w] = m;
    }
    __syncthreads();
    if (act && wt == 0) {
        float mc = red[gbase];
        for (int i = 1; i < 8; i++) mc = fminf(mc, red[gbase + i]);
        sh_mc2[bb] = mc;
    }
    __syncthreads();

    // ---- nearest valid point BELOW bin wt: prefix-max of gap maxes 0..wt ----
    float below = (mb == 0u) ? -3e18f : __uint_as_float(mb);
#pragma unroll
    for (int o = 1; o < 32; o <<= 1) {
        float uu = __shfl_up_sync(0xffffffffu, below, o);
        if (lane >= o) below = fmaxf(below, uu);
    }
    if (lane == 31) red2[w] = below;
    __syncthreads();
    {
        float carry = -3e18f;
        for (int i = 0; i < wiw; i++) carry = fmaxf(carry, red2[gbase + i]);
        below = fmaxf(below, carry);
    }
    __syncthreads();

    // ---- nearest valid point ABOVE bin j: suffix-min of gap mins j+1..256 ----
    float above = (na == 0u) ? 3e18f : __uint_as_float(~na);
#pragma unroll
    for (int o = 1; o < 32; o <<= 1) {
        float uu = __shfl_up_sync(0xffffffffu, above, o);
        if (lane >= o) above = fminf(above, uu);
    }
    if (lane == 31) red2[w] = above;
    __syncthreads();
    {
        float carry2 = 3e18f;
        for (int i = 0; i < wiw; i++) carry2 = fminf(carry2, red2[gbase + i]);
        above = fminf(above, carry2);
    }
    s_above[t] = above;
    __syncthreads();

    // ---- per-bin minima + sums ----
    float mv1 = 0.0f, mv2 = 0.0f;
    if (act) {
        float ab = s_above[(t & ~255) + (NB - 1 - wt)];
        float d1 = c - below;          // sentinels -> ~9e36, never the min
        float d2 = ab - c;
        mv1 = fminf(d1 * d1, d2 * d2); // min over valid points
        mv2 = fminf(mv1, c2);          // incl. zero pad-point candidate
    }
#pragma unroll
    for (int o = 16; o; o >>= 1) {
        mv1 += __shfl_down_sync(0xffffffffu, mv1, o);
        mv2 += __shfl_down_sync(0xffffffffu, mv2, o);
    }
    if (lane == 0) { red[w] = mv1; red2[w] = mv2; }
    __syncthreads();
    if (act && wt == 0) {
        float S1 = 0.0f, S2 = 0.0f;
        for (int i = 0; i < 8; i++) { S1 += red[gbase + i]; S2 += red2[gbase + i]; }
        sh_S1[bb] = S1; sh_S2[bb] = S2;
    }
    __syncthreads();

    if (t == 0) {
        float Lmax = 0.0f;
        for (int bb2 = 0; bb2 < B; bb2++) Lmax = fmaxf(Lmax, sh_n[bb2]);
        float total = 0.0f;
        for (int bb2 = 0; bb2 < B; bb2++) {
            float npad = Lmax - sh_n[bb2];
            total += sh_sA[bb2] + npad * sh_mc2[bb2]
                   + ((npad > 0.0f) ? sh_S2[bb2] : sh_S1[bb2]);
        }
        out[0] = total / (float)B;
    }

    // ---- reset all scratch for next replay (all reads above complete) ------------------
    __syncthreads();
    for (int i = t; i < B * NGAP; i += BLOCK) {
        g_gapmax [i * GAPSTRIDE] = 0u;
        g_gapminN[i * GAPSTRIDE] = 0u;
    }
    if (t == 0) g_arrive = 0u;
}

// -----------------------------------------------------------------------------
extern "C" void kernel_launch(void* const* d_in, const int* in_sizes, int n_in,
                              void* d_out, int out_size)
{
    const float* bins = (const float*)d_in[0];
    const float* pts  = (const float*)d_in[1];
    int sb = in_sizes[0], sp = in_sizes[1];
    if (sb > sp) {                 // defensive: detect swapped input order
        const float* tmp = bins; bins = pts; pts = tmp;
        int ts = sb; sb = sp; sp = ts;
    }
    int B = sb / NB;               // 4
    int V = sp / B;                // 157696

    dim3 grid(BPB, B);
    k_all<<<grid, BLOCK>>>(bins, pts, V, B, (float*)d_out);
}

// round 15
// speedup vs baseline: 1.0348x; 1.0213x over previous
#include <cuda_runtime.h>

#define NB        256            // bins per batch
#define TB        512            // bucket-table size
#define BLOCK     1024           // threads per block
#define BPB       74             // blocks per batch: 4*74=296 = 2/SM, 64 warps/SM
#define MAXB      8
#define NGAP      (NB + 1)
#define GAPSTRIDE 8              // 32B per global gap slot

// group-scoped named barrier: 8 warps (256 threads) of one batch-group
#define GROUP_BAR(gid) asm volatile("bar.sync %0, 256;" :: "r"((gid) + 1) : "memory")

// Static zero-init scratch; counters/gap slots reset in-kernel before exit.
__device__ unsigned g_gapmax [MAXB * NGAP * GAPSTRIDE];  // max of float bits (pv>0)
__device__ unsigned g_gapminN[MAXB * NGAP * GAPSTRIDE];  // max of ~bits
__device__ float    g_sorted[MAXB * NB];
__device__ float    g_psum[MAXB * BPB];
__device__ float    g_pcnt[MAXB * BPB];
__device__ unsigned g_arrive;

__device__ __forceinline__ float vldf(const float* p) { return *(const volatile float*)p; }
__device__ __forceinline__ unsigned vldu(const unsigned* p) { return *(const volatile unsigned*)p; }

// per-point hot path: 1 LDS.128 table + predicate select + 1 LDS.64 gap check.
__device__ __forceinline__ void ppoint(
    float pv, const uint4* __restrict__ tab, const float* __restrict__ sc,
    uint2* gap, float lo, float scale, float& sumA, float& cnt)
{
    int k = __float2int_rd((pv - lo) * scale);
    k = min(TB - 1, max(k, 0));
    uint4 e = tab[k];
    int g; float cl, cr;
    if (e.w >> 16) {                      // boundary bucket (>=2 bins): short narrow
        int a = (int)(e.w & 0xffffu), b2 = (int)(e.w >> 16);
        while (a < b2) { int m = (a + b2) >> 1; if (sc[m] <= pv) a = m + 1; else b2 = m; }
        g = a;
        cl = (g > 0)  ? sc[g - 1] : -3e18f;
        cr = (g < NB) ? sc[g]     :  3e18f;
    } else {
        float cm = __uint_as_float(e.y);
        bool pr = pv >= cm;               // ties: bin <= pv counts -> g+1
        cl = pr ? cm : __uint_as_float(e.x);
        cr = pr ? __uint_as_float(e.z) : cm;
        g = (int)e.w + (pr ? 1 : 0);
    }
    float dlo = pv - cl, dhi = cr - pv;
    float d = fminf(dlo * dlo, dhi * dhi);
    if (pv >= 0.001f) {                   // same mask constant as reference
        sumA += d; cnt += 1.0f;
        unsigned pb = __float_as_uint(pv);        // pv>0: uint order == float order
        uint2 cur = gap[g];
        if (pb > cur.x)  atomicMax(&gap[g].x, pb);   // monotonic -> stale-skip safe
        unsigned nb2 = ~pb;
        if (nb2 > cur.y) atomicMax(&gap[g].y, nb2);
    }
}

__global__ void __launch_bounds__(BLOCK, 2)
k_all(const float* __restrict__ bins, const float* __restrict__ pts,
      int V, int B, float* __restrict__ out)
{
    __shared__ __align__(16) union {
        uint4 tab[TB];                    // 8 KB, final
        int   hist[TB];                   // 2 KB, prep
    } u;
    __shared__ unsigned short Gt[TB + 1];
    __shared__ float          sc[NB];
    __shared__ uint2          gap[NGAP];
    __shared__ float          redA[32], redB[32], redC[32];
    __shared__ float          redD[32], redE[32], redF[32], redG[32];
    __shared__ float          s_above[BLOCK];     // 4 groups x 256
    __shared__ float          sh_sA[MAXB], sh_n[MAXB], sh_mc2[MAXB];
    __shared__ float          sh_S1[MAXB], sh_S2[MAXB];
    __shared__ float          s_lo, s_scale;
    __shared__ int            s_fin;

    const int b = blockIdx.y, bx = blockIdx.x, t = threadIdx.x;
    const int lane = t & 31, w = t >> 5;

    // ---- prefetch this thread's points as float2 (overlaps with prep) --------
    const float* pf = pts + (size_t)b * V;
    const int V2 = V >> 1;                // 78848
    const float2* p2 = reinterpret_cast<const float2*>(pf);
    const int S = BPB * BLOCK;            // 75776
    const int i0 = bx * BLOCK + t;        // < 75776 <= V2 always
    float2 q0, q1;
    const bool v1 = i0 + S < V2;          // first 3072 threads only
    q0 = p2[i0];
    if (v1) q1 = p2[i0 + S];

    // ---- bins in registers; init hist + gap tallies ----------------------------
    const bool isbin = t < NB;
    float bv = isbin ? bins[b * NB + t] : 0.0f;
    if (t < TB) u.hist[t] = 0;
    if (t < NGAP) gap[t] = make_uint2(0u, 0u);

    // ---- min/max of bins -> bucket transform ------------------------------------
    {
        float mn = isbin ? bv :  3e18f;
        float mx = isbin ? bv : -3e18f;
#pragma unroll
        for (int o = 16; o; o >>= 1) {
            mn = fminf(mn, __shfl_down_sync(0xffffffffu, mn, o));
            mx = fmaxf(mx, __shfl_down_sync(0xffffffffu, mx, o));
        }
        if (lane == 0 && w < 8) { redA[w] = mn; redB[w] = mx; }
    }
    __syncthreads();                       // also covers hist/gap init
    if (w == 0) {                          // warp 0 combines 8 partials by shuffle
        float mn = (lane < 8) ? redA[lane] :  3e18f;
        float mx = (lane < 8) ? redB[lane] : -3e18f;
#pragma unroll
        for (int o = 4; o; o >>= 1) {
            mn = fminf(mn, __shfl_down_sync(0xffffffffu, mn, o));
            mx = fmaxf(mx, __shfl_down_sync(0xffffffffu, mx, o));
        }
        if (lane == 0) {
            float d = mx - mn;
            s_lo = mn;
            s_scale = (d > 1e-30f) ? ((float)TB / d) : 0.0f;
        }
    }
    __syncthreads();
    const float lo = s_lo, scale = s_scale;

    // ---- histogram of bin buckets -------------------------------------------------
    int kbv = 0;
    if (isbin) {
        kbv = __float2int_rd((bv - lo) * scale);
        kbv = min(TB - 1, max(kbv, 0));
        atomicAdd(&u.hist[kbv], 1);
    }
    __syncthreads();

    // ---- exclusive scan hist -> Gt (two-level shuffle scan, 16 warps) ---------------
    {
        int h = 0, incl = 0;
        if (t < TB) {
            h = u.hist[t];
            u.hist[t] = 0;                // reuse as slot counters
            incl = h;
#pragma unroll
            for (int o = 1; o < 32; o <<= 1) {
                int uu = __shfl_up_sync(0xffffffffu, incl, o);
                if (lane >= o) incl += uu;
            }
            if (lane == 31) redA[w] = __int_as_float(incl);
        }
        __syncthreads();
        if (w == 0) {                     // warp 0: exclusive scan of 16 partials
            int v = (lane < TB / 32) ? __float_as_int(redA[lane]) : 0;
            int si = v;
#pragma unroll
            for (int o = 1; o < 32; o <<= 1) {
                int uu = __shfl_up_sync(0xffffffffu, si, o);
                if (lane >= o) si += uu;
            }
            redA[lane] = __int_as_float(si - v);
        }
        __syncthreads();
        if (t < TB) {
            int base = __float_as_int(redA[w]) + incl - h;
            Gt[t] = (unsigned short)base;
            if (t == TB - 1) Gt[TB] = (unsigned short)(base + h);
        }
    }
    __syncthreads();

    // ---- placement: atomic slot within bucket; O(m) re-rank for collisions ---------
    int aslot = 0, abase = 0, mcount = 0;
    if (isbin) {
        abase = Gt[kbv];
        mcount = Gt[kbv + 1] - abase;
        int off = (mcount == 1) ? 0 : atomicAdd(&u.hist[kbv], 1);
        aslot = abase + off;
        sc[aslot] = bv;
    }
    __syncthreads();
    int rrank = 0;
    if (isbin && mcount > 1) {
        for (int j = abase; j < abase + mcount; j++) {
            float vj = sc[j];
            rrank += (vj < bv) || (vj == bv && j < aslot);
        }
    }
    __syncthreads();
    if (isbin && mcount > 1) sc[abase + rrank] = bv;
    __syncthreads();

    // ---- three-candidate direct-answer table (threads < TB) --------------------------
    if (t < TB) {
        int k = t;
        int a = Gt[k], b2 = Gt[k + 1], m = b2 - a;
        uint4 e;
        if (m <= 1) {
            float prev = (a > 0) ? sc[a - 1] : -3e18f;
            if (m == 0) {
                float cr = (a < NB) ? sc[a] : 3e18f;
                e.x = __float_as_uint(prev); e.y = __float_as_uint(cr);
                e.z = __float_as_uint(cr);   e.w = (unsigned)a;
            } else {
                float cm  = sc[a];
                float nxt = (a + 1 < NB) ? sc[a + 1] : 3e18f;
                e.x = __float_as_uint(prev); e.y = __float_as_uint(cm);
                e.z = __float_as_uint(nxt);  e.w = (unsigned)a;
            }
        } else {
            e.x = 0u; e.y = 0u; e.z = 0u;
            e.w = (unsigned)a | ((unsigned)b2 << 16);
        }
        u.tab[k] = e;
    }
    __syncthreads();

    // ================= MAIN PASS ======================================================
    float sumA = 0.0f, cnt = 0.0f;
    ppoint(q0.x, u.tab, sc, gap, lo, scale, sumA, cnt);
    ppoint(q0.y, u.tab, sc, gap, lo, scale, sumA, cnt);
    if (v1) {
        ppoint(q1.x, u.tab, sc, gap, lo, scale, sumA, cnt);
        ppoint(q1.y, u.tab, sc, gap, lo, scale, sumA, cnt);
    }
    for (int i = i0 + 2 * S; i < V2; i += S) {   // generic remainder (unused here)
        float2 q = p2[i];
        ppoint(q.x, u.tab, sc, gap, lo, scale, sumA, cnt);
        ppoint(q.y, u.tab, sc, gap, lo, scale, sumA, cnt);
    }
    if (bx == 0 && t == 0 && (V & 1))
        ppoint(pf[V - 1], u.tab, sc, gap, lo, scale, sumA, cnt);

    // ---- block reduction of sumA / cnt (two-level shuffle) ---------------------------
#pragma unroll
    for (int o = 16; o; o >>= 1) {
        sumA += __shfl_down_sync(0xffffffffu, sumA, o);
        cnt  += __shfl_down_sync(0xffffffffu, cnt,  o);
    }
    if (lane == 0) { redA[w] = sumA; redB[w] = cnt; }
    __syncthreads();
    if (w == 0) {                         // warp 0 reduces 32 partials
        float s = redA[lane], c = redB[lane];
#pragma unroll
        for (int o = 16; o; o >>= 1) {
            s += __shfl_down_sync(0xffffffffu, s, o);
            c += __shfl_down_sync(0xffffffffu, c, o);
        }
        if (lane == 0) {
            g_psum[b * BPB + bx] = s;
            g_pcnt[b * BPB + bx] = c;
        }
    }

    // ---- flush shared gap tallies + publish sorted bins --------------------------------
    if (t < NGAP) {
        uint2 v = gap[t];
        if (v.x) atomicMax(&g_gapmax [(b * NGAP + t) * GAPSTRIDE], v.x);
        if (v.y) atomicMax(&g_gapminN[(b * NGAP + t) * GAPSTRIDE], v.y);
    }
    if (bx == 0 && t < NB) g_sorted[b * NB + t] = sc[t];

    // ---- single global arrival: last block of ALL does fused finalize ------------------
    __threadfence();
    __syncthreads();
    if (t == 0) {
        unsigned total = gridDim.x * gridDim.y;
        unsigned old = atomicAdd(&g_arrive, 1u);
        s_fin = (old == total - 1u) ? 1 : 0;
    }
    __syncthreads();
    if (!s_fin) return;
    __threadfence();

    // ================= FUSED FINALIZE: 4 independent batch-groups (named barriers) ======
    const int wt  = t & 255;              // bin index within group
    const int wiw = (t >> 5) & 7;         // warp within group (0..7)
    const int NWP = (BPB + 31) / 32;      // warps holding psum partials
    const int bb  = t >> 8;               // batch handled by this group (B==4)
    const bool act = bb < B;
    const int gbase = bb * 8;             // this group's warps in red arrays

    // ---- bulk loads (independent LDGs -> one latency) ----
    float ps = 0.0f, pc = 0.0f;
    if (act && wt < BPB) { ps = vldf(&g_psum[bb * BPB + wt]); pc = vldf(&g_pcnt[bb * BPB + wt]); }
    float c = act ? vldf(&g_sorted[bb * NB + wt]) : 3e18f;
    unsigned mb = act ? vldu(&g_gapmax [(bb * NGAP + wt) * GAPSTRIDE]) : 0u;
    unsigned na = act ? vldu(&g_gapminN[(bb * NGAP + (NB - wt)) * GAPSTRIDE]) : 0u;
    float c2 = act ? c * c : 3e18f;

    // ---- PHASE 1: all warp-local reductions/scans at once (ILP, no hazards) ----
    {
        float s = ps, cc = pc, m = c2;
#pragma unroll
        for (int o = 16; o; o >>= 1) {
            s  += __shfl_down_sync(0xffffffffu, s,  o);
            cc += __shfl_down_sync(0xffffffffu, cc, o);
            m = fminf(m, __shfl_down_sync(0xffffffffu, m, o));
        }
        if (lane == 0) { redA[w] = s; redB[w] = cc; redC[w] = m; }
    }
    float below = (mb == 0u) ? -3e18f : __uint_as_float(mb);
    float above = (na == 0u) ?  3e18f : __uint_as_float(~na);
#pragma unroll
    for (int o = 1; o < 32; o <<= 1) {
        float ub = __shfl_up_sync(0xffffffffu, below, o);
        float ua = __shfl_up_sync(0xffffffffu, above, o);
        if (lane >= o) { below = fmaxf(below, ub); above = fminf(above, ua); }
    }
    if (lane == 31) { redD[w] = below; redE[w] = above; }
    GROUP_BAR(bb);

    // ---- PHASE 2: cross-warp carries + leader scalar combines ----
    {
        float carry = -3e18f, carry2 = 3e18f;
        for (int i = 0; i < wiw; i++) {
            carry  = fmaxf(carry,  redD[gbase + i]);
            carry2 = fminf(carry2, redE[gbase + i]);
        }
        below = fmaxf(below, carry);
        above = fminf(above, carry2);
    }
    s_above[t] = above;
    if (act && wt == 0) {
        float ss = 0.0f, cc = 0.0f;
        for (int i = 0; i < NWP; i++) { ss += redA[gbase + i]; cc += redB[gbase + i]; }
        float mc = redC[gbase];
        for (int i = 1; i < 8; i++) mc = fminf(mc, redC[gbase + i]);
        sh_sA[bb] = ss; sh_n[bb] = cc; sh_mc2[bb] = mc;
    }
    GROUP_BAR(bb);

    // ---- PHASE 3: per-bin minima + sums ----
    float mv1 = 0.0f, mv2 = 0.0f;
    if (act) {
        float ab = s_above[(t & ~255) + (NB - 1 - wt)];
        float d1 = c - below;          // sentinels -> ~9e36, never the min
        float d2 = ab - c;
        mv1 = fminf(d1 * d1, d2 * d2); // min over valid points
        mv2 = fminf(mv1, c2);          // incl. zero pad-point candidate
    }
#pragma unroll
    for (int o = 16; o; o >>= 1) {
        mv1 += __shfl_down_sync(0xffffffffu, mv1, o);
        mv2 += __shfl_down_sync(0xffffffffu, mv2, o);
    }
    if (lane == 0) { redF[w] = mv1; redG[w] = mv2; }
    GROUP_BAR(bb);
    if (act && wt == 0) {
        float S1 = 0.0f, S2 = 0.0f;
        for (int i = 0; i < 8; i++) { S1 += redF[gbase + i]; S2 += redG[gbase + i]; }
        sh_S1[bb] = S1; sh_S2[bb] = S2;
    }
    __syncthreads();                      // all groups done before combine/reset

    if (t == 0) {
        float Lmax = 0.0f;
        for (int bb2 = 0; bb2 < B; bb2++) Lmax = fmaxf(Lmax, sh_n[bb2]);
        float total = 0.0f;
        for (int bb2 = 0; bb2 < B; bb2++) {
            float npad = Lmax - sh_n[bb2];
            total += sh_sA[bb2] + npad * sh_mc2[bb2]
                   + ((npad > 0.0f) ? sh_S2[bb2] : sh_S1[bb2]);
        }
        out[0] = total / (float)B;
    }

    // ---- reset all scratch for next replay (all reads above complete) ------------------
    for (int i = t; i < B * NGAP; i += BLOCK) {
        g_gapmax [i * GAPSTRIDE] = 0u;
        g_gapminN[i * GAPSTRIDE] = 0u;
    }
    if (t == 1) g_arrive = 0u;
}

// -----------------------------------------------------------------------------
extern "C" void kernel_launch(void* const* d_in, const int* in_sizes, int n_in,
                              void* d_out, int out_size)
{
    const float* bins = (const float*)d_in[0];
    const float* pts  = (const float*)d_in[1];
    int sb = in_sizes[0], sp = in_sizes[1];
    if (sb > sp) {                 // defensive: detect swapped input order
        const float* tmp = bins; bins = pts; pts = tmp;
        int ts = sb; sb = sp; sp = ts;
    }
    int B = sb / NB;               // 4
    int V = sp / B;                // 157696

    dim3 grid(BPB, B);
    k_all<<<grid, BLOCK>>>(bins, pts, V, B, (float*)d_out);
}